// round 3
// baseline (speedup 1.0000x reference)
#include <cuda_runtime.h>

// Problem constants
#define BATCH 8
#define C_IN  256
#define C_MID 1024
#define HW    4096   // 64*64
#define PHW   1024   // 32*32

// ---------------- scratch (static device globals; no allocation) ----------------
__device__ float g_Y [(size_t)BATCH * C_MID * HW];    // 128 MiB conv scratch
__device__ float g_Fa[(size_t)BATCH * C_MID * PHW];   // 32 MiB
__device__ float g_Fb[(size_t)BATCH * C_MID * PHW];
__device__ float g_G [(size_t)BATCH * C_MID * PHW];
__device__ float g_M [(size_t)BATCH * PHW * PHW];
__device__ float g_E [(size_t)BATCH * PHW * C_MID];
__device__ float g_V [(size_t)BATCH * 256 * PHW];     // 8 MiB

// ---------------- generic strided fp32 GEMM: C[i,j] = sum_k A(i,k)*B(k,j) (+bias[i])
// A(i,k) at A[i*saR + k*saK] (+ bz*saB), B(k,j) at B[k*sbK + j*sbC] (+ bz*sbB)
// C row-major ldc (+ bz*scB).
// Tile: 128x128 per CTA, 8x8 per thread, K-step 16, register-prefetch double buffer.
// M,N divisible by 128, K divisible by 32 (>=2 k-steps).
__global__ __launch_bounds__(256, 1) void gemm128(
    const float* __restrict__ A, long saR, long saK, long saB,
    const float* __restrict__ B, long sbK, long sbC, long sbB,
    float* __restrict__ C, long ldc, long scB,
    int K, const float* __restrict__ bias)
{
    __shared__ float As[16][132];
    __shared__ float Bs[16][132];
    float* Asf = &As[0][0];
    float* Bsf = &Bs[0][0];

    const int bz = blockIdx.z;
    A += (long)bz * saB;
    B += (long)bz * sbB;
    C += (long)bz * scB;
    const int i0 = blockIdx.y * 128;
    const int j0 = blockIdx.x * 128;
    const int tid = threadIdx.x;
    const int tx = tid & 15, ty = tid >> 4;

    const bool aKfast = (saK == 1);
    const bool bKfast = (sbK == 1);

    // Precompute per-thread load pointers + smem store offsets (8 elems each side).
    const float* pa[8]; int sa_off[8];
    const float* pb[8]; int sb_off[8];
    const long a_step = aKfast ? 16 : 16 * saK;
    const long b_step = bKfast ? 16 : 16 * sbK;
#pragma unroll
    for (int t = 0; t < 8; t++) {
        int idx = tid + t * 256;
        int kk, ii;
        if (aKfast) { kk = idx & 15; ii = idx >> 4; }
        else        { ii = idx & 127; kk = idx >> 7; }
        pa[t] = A + (long)(i0 + ii) * saR + (aKfast ? (long)kk : (long)kk * saK);
        sa_off[t] = kk * 132 + ii;
        int kb, jj;
        if (bKfast) { kb = idx & 15; jj = idx >> 4; }
        else        { jj = idx & 127; kb = idx >> 7; }
        pb[t] = B + (long)(j0 + jj) * sbC + (bKfast ? (long)kb : (long)kb * sbK);
        sb_off[t] = kb * 132 + jj;
    }

    float acc[8][8];
#pragma unroll
    for (int r = 0; r < 8; r++)
#pragma unroll
        for (int c = 0; c < 8; c++) acc[r][c] = 0.f;

    // Prefetch first tile into registers.
    float ra[8], rb[8];
#pragma unroll
    for (int t = 0; t < 8; t++) { ra[t] = *pa[t]; rb[t] = *pb[t]; }

    for (int k0 = 0; k0 < K; k0 += 16) {
        // Commit staged tile to smem.
#pragma unroll
        for (int t = 0; t < 8; t++) {
            Asf[sa_off[t]] = ra[t];
            Bsf[sb_off[t]] = rb[t];
        }
        __syncthreads();

        // Prefetch next tile while computing this one.
        if (k0 + 16 < K) {
#pragma unroll
            for (int t = 0; t < 8; t++) {
                pa[t] += a_step; ra[t] = *pa[t];
                pb[t] += b_step; rb[t] = *pb[t];
            }
        }

#pragma unroll
        for (int kk = 0; kk < 16; kk++) {
            float4 a0 = *reinterpret_cast<const float4*>(&As[kk][ty * 8]);
            float4 a1 = *reinterpret_cast<const float4*>(&As[kk][ty * 8 + 4]);
            float4 b0 = *reinterpret_cast<const float4*>(&Bs[kk][tx * 8]);
            float4 b1 = *reinterpret_cast<const float4*>(&Bs[kk][tx * 8 + 4]);
            float a[8] = {a0.x, a0.y, a0.z, a0.w, a1.x, a1.y, a1.z, a1.w};
            float b[8] = {b0.x, b0.y, b0.z, b0.w, b1.x, b1.y, b1.z, b1.w};
#pragma unroll
            for (int r = 0; r < 8; r++)
#pragma unroll
                for (int c = 0; c < 8; c++)
                    acc[r][c] += a[r] * b[c];
        }
        __syncthreads();
    }

#pragma unroll
    for (int r = 0; r < 8; r++) {
        int i = i0 + ty * 8 + r;
        float bv = bias ? bias[i] : 0.f;
        float4 o0, o1;
        o0.x = acc[r][0] + bv; o0.y = acc[r][1] + bv;
        o0.z = acc[r][2] + bv; o0.w = acc[r][3] + bv;
        o1.x = acc[r][4] + bv; o1.y = acc[r][5] + bv;
        o1.z = acc[r][6] + bv; o1.w = acc[r][7] + bv;
        float* cp = &C[(long)i * ldc + j0 + tx * 8];
        *reinterpret_cast<float4*>(cp)     = o0;
        *reinterpret_cast<float4*>(cp + 4) = o1;
    }
}

// ---------------- 2x2 maxpool: Y [bc][64][64] -> F [bc][32][32] ----------------
__global__ void pool_kernel(const float* __restrict__ Y, float* __restrict__ F)
{
    long i = (long)blockIdx.x * blockDim.x + threadIdx.x;  // over BATCH*C_MID*PHW
    int ow = (int)(i & 31);
    int oh = (int)((i >> 5) & 31);
    long co = i >> 10;  // b*C_MID + c
    const float* y = Y + co * 4096 + (long)(oh * 2) * 64 + ow * 2;
    float v = fmaxf(fmaxf(y[0], y[1]), fmaxf(y[64], y[65]));
    F[i] = v;
}

// ---------------- relu + L2 row-normalize (rows of 1024) ----------------
__global__ void norm_kernel(float* __restrict__ Mb)
{
    long row = blockIdx.x;
    float* p = Mb + row * 1024;
    int t = threadIdx.x;  // 256
    float v[4];
    float ss = 0.f;
#pragma unroll
    for (int r = 0; r < 4; r++) {
        float x = p[t + 256 * r];
        x = fmaxf(x, 0.f);
        v[r] = x;
        ss += x * x;
    }
#pragma unroll
    for (int o = 16; o > 0; o >>= 1) ss += __shfl_xor_sync(0xffffffffu, ss, o);
    __shared__ float sred[8];
    if ((t & 31) == 0) sred[t >> 5] = ss;
    __syncthreads();
    if (t < 32) {
        float s = (t < 8) ? sred[t] : 0.f;
#pragma unroll
        for (int o = 4; o > 0; o >>= 1) s += __shfl_xor_sync(0xffffffffu, s, o);
        if (t == 0) sred[0] = s;
    }
    __syncthreads();
    float inv = rsqrtf(sred[0] + 1e-6f);
#pragma unroll
    for (int r = 0; r < 4; r++) p[t + 256 * r] = v[r] * inv;
}

// ---------------- 2x bilinear upsample (align_corners): V [bc][32][32] -> O [bc][64][64]
__global__ void upsample_kernel(const float* __restrict__ V, float* __restrict__ O)
{
    long i = (long)blockIdx.x * blockDim.x + threadIdx.x;  // over BATCH*256*HW
    int x = (int)(i & 63);
    int y = (int)((i >> 6) & 63);
    long co = i >> 12;  // b*256 + o
    const float s = 31.0f / 63.0f;
    float ys = y * s;
    float xs = x * s;
    int y0 = (int)floorf(ys);
    int x0 = (int)floorf(xs);
    float ty = ys - (float)y0;
    float txx = xs - (float)x0;
    int y1 = min(y0 + 1, 31);
    int x1 = min(x0 + 1, 31);
    const float* v = V + co * 1024;
    float v00 = v[y0 * 32 + x0];
    float v01 = v[y0 * 32 + x1];
    float v10 = v[y1 * 32 + x0];
    float v11 = v[y1 * 32 + x1];
    O[i] = (1.f - ty) * ((1.f - txx) * v00 + txx * v01) +
           ty * ((1.f - txx) * v10 + txx * v11);
}

// ---------------- launch ----------------
extern "C" void kernel_launch(void* const* d_in, const int* in_sizes, int n_in,
                              void* d_out, int out_size)
{
    const float* xa      = (const float*)d_in[0];
    const float* xb      = (const float*)d_in[1];
    const float* conv_w  = (const float*)d_in[2];   // (1024,256)
    const float* conv_b  = (const float*)d_in[3];   // (1024,)
    const float* We      = (const float*)d_in[4];   // (1024,1024)
    const float* We2     = (const float*)d_in[5];   // (1024,1024)
    const float* conv2_w = (const float*)d_in[6];   // (256,1024)
    const float* conv2_b = (const float*)d_in[7];   // (256,)
    float* out = (float*)d_out;

    float *Y, *Fa, *Fb, *G, *M, *E, *V;
    cudaGetSymbolAddress((void**)&Y,  g_Y);
    cudaGetSymbolAddress((void**)&Fa, g_Fa);
    cudaGetSymbolAddress((void**)&Fb, g_Fb);
    cudaGetSymbolAddress((void**)&G,  g_G);
    cudaGetSymbolAddress((void**)&M,  g_M);
    cudaGetSymbolAddress((void**)&E,  g_E);
    cudaGetSymbolAddress((void**)&V,  g_V);

    const long MM = (long)1024 * 1024;
    dim3 blk(256);

    // --- conv1x1 + pool for xa -> Fa ---
    gemm128<<<dim3(HW / 128, C_MID / 128, BATCH), blk>>>(
        conv_w, 256, 1, 0,
        xa, HW, 1, (long)C_IN * HW,
        Y, HW, (long)C_MID * HW, C_IN, conv_b);
    pool_kernel<<<(BATCH * C_MID * PHW) / 256, 256>>>(Y, Fa);

    // --- conv1x1 + pool for xb -> Fb ---
    gemm128<<<dim3(HW / 128, C_MID / 128, BATCH), blk>>>(
        conv_w, 256, 1, 0,
        xb, HW, 1, (long)C_IN * HW,
        Y, HW, (long)C_MID * HW, C_IN, conv_b);
    pool_kernel<<<(BATCH * C_MID * PHW) / 256, 256>>>(Y, Fb);

    for (int path = 0; path < 2; path++) {
        const float* Wx   = (path == 0) ? We : We2;
        const float* Fsrc = (path == 0) ? Fa : Fb;  // G = Wx^T @ Fsrc ; en uses Fsrc
        const float* Foth = (path == 0) ? Fb : Fa;  // fm = Foth^T @ G

        // G[c,q] = sum_d Wx[d,c] * Fsrc[d,q]
        gemm128<<<dim3(8, 8, BATCH), blk>>>(
            Wx, 1, 1024, 0,
            Fsrc, 1024, 1, MM,
            G, 1024, MM, 1024, nullptr);

        // fm[p,q] = sum_c Foth[c,p] * G[c,q]
        gemm128<<<dim3(8, 8, BATCH), blk>>>(
            Foth, 1, 1024, MM,
            G, 1024, 1, MM,
            M, 1024, MM, 1024, nullptr);

        // relu + row-L2-normalize over q (axis 2 of fm)
        norm_kernel<<<BATCH * 1024, 256>>>(M);

        // E[q,k] = sum_p M[p,q] * Fsrc[k,p]
        gemm128<<<dim3(8, 8, BATCH), blk>>>(
            M, 1, 1024, MM,
            Fsrc, 1, 1024, MM,
            E, 1024, MM, 1024, nullptr);

        // V[o,s] = sum_q conv2_w[o,q] * E[q,s] + conv2_b[o]   (conv before upsample;
        // en's "channel" axis after the reference reshape is q, spatial is k)
        gemm128<<<dim3(8, 2, BATCH), blk>>>(
            conv2_w, 1024, 1, 0,
            E, 1024, 1, MM,
            V, 1024, (long)256 * PHW, 1024, conv2_b);

        // upsample 2x align_corners -> output half
        upsample_kernel<<<(BATCH * 256 * HW) / 256, 256>>>(
            V, out + (long)path * BATCH * 256 * HW);
    }
}

// round 5
// speedup vs baseline: 2.3476x; 2.3476x over previous
#include <cuda_runtime.h>
#include <cuda_bf16.h>
#include <cstdint>

#define BATCH 8
#define C_IN  256
#define C_MID 1024
#define HW    4096   // 64*64
#define PHW   1024   // 32*32

// ---------------- scratch (static device globals; no allocation) ----------------
__device__ float g_XT [(size_t)BATCH * HW * C_IN];     // x transposed [pix][c]
__device__ float g_Y  [(size_t)BATCH * C_MID * HW];    // conv1 out
__device__ float g_Fa [(size_t)BATCH * C_MID * PHW];   // pooled features [c][q]
__device__ float g_Fb [(size_t)BATCH * C_MID * PHW];
__device__ float g_FaT[(size_t)BATCH * PHW * C_MID];   // [q][c]
__device__ float g_FbT[(size_t)BATCH * PHW * C_MID];
__device__ float g_WT [(size_t)C_MID * C_MID];         // We / We2 transposed
__device__ float g_GT [(size_t)BATCH * PHW * C_MID];   // GT[q][c]
__device__ float g_MT [(size_t)BATCH * PHW * PHW];     // fmT[q][p] -> normalized
__device__ float g_ET [(size_t)BATCH * PHW * C_MID];   // ET[chan][q]
__device__ float g_V  [(size_t)BATCH * 256 * PHW];

// ================= warp-MMA helpers (plain PTX, no 'a'-target features) =========
__device__ __forceinline__ uint32_t smem_u32(const void* p) {
    uint32_t a;
    asm("{ .reg .u64 t; cvta.to.shared.u64 t, %1; cvt.u32.u64 %0, t; }" : "=r"(a) : "l"(p));
    return a;
}

__device__ __forceinline__ void ldsm4(uint32_t* r, uint32_t addr) {
    asm volatile("ldmatrix.sync.aligned.m8n8.x4.shared.b16 {%0,%1,%2,%3}, [%4];"
                 : "=r"(r[0]), "=r"(r[1]), "=r"(r[2]), "=r"(r[3]) : "r"(addr));
}

__device__ __forceinline__ void mma16816(float* d, const uint32_t* a, const uint32_t* b) {
    asm volatile(
        "mma.sync.aligned.m16n8k16.row.col.f32.bf16.bf16.f32 "
        "{%0,%1,%2,%3}, {%4,%5,%6,%7}, {%8,%9}, {%0,%1,%2,%3};"
        : "+f"(d[0]), "+f"(d[1]), "+f"(d[2]), "+f"(d[3])
        : "r"(a[0]), "r"(a[1]), "r"(a[2]), "r"(a[3]), "r"(b[0]), "r"(b[1]));
}

// ================= tensor GEMM via mma.sync =================
// C[i,j] (+bias[i]) = sum_k A[i*lda+k] * B[j*ldb+k]   (both operands K-contiguous)
// CTA tile 128x128, 8 warps (2m x 4n), warp tile 64x32, K-chunk 32, bf16 3-term split.
#define KC        32
#define ROWS_B16  40           // 32 + 8 pad -> 80B row stride, conflict-free ldmatrix
#define ARR_B     10240        // 128 * 40 * 2 bytes
#define STG_B     40960        // Ah Al Bh Bl
#define SM_TOTAL  81920        // 2 stages

__device__ __forceinline__ void split4(float4 v, uint32_t& hp0, uint32_t& hp1,
                                       uint32_t& lp0, uint32_t& lp1) {
    asm("cvt.rn.bf16x2.f32 %0, %1, %2;" : "=r"(hp0) : "f"(v.y), "f"(v.x));
    asm("cvt.rn.bf16x2.f32 %0, %1, %2;" : "=r"(hp1) : "f"(v.w), "f"(v.z));
    float h0 = __uint_as_float(hp0 << 16);
    float h1 = __uint_as_float(hp0 & 0xFFFF0000u);
    float h2 = __uint_as_float(hp1 << 16);
    float h3 = __uint_as_float(hp1 & 0xFFFF0000u);
    asm("cvt.rn.bf16x2.f32 %0, %1, %2;" : "=r"(lp0) : "f"(v.y - h1), "f"(v.x - h0));
    asm("cvt.rn.bf16x2.f32 %0, %1, %2;" : "=r"(lp1) : "f"(v.w - h3), "f"(v.z - h2));
}

__global__ __launch_bounds__(256, 1) void tgemm(
    const float* __restrict__ A, long lda, long saB,
    const float* __restrict__ B, long ldb, long sbB,
    float* __restrict__ C, long ldc, long scB,
    int K, const float* __restrict__ bias)
{
    extern __shared__ char smem[];
    const uint32_t s0 = smem_u32(smem);
    const int tid = threadIdx.x;
    const int lane = tid & 31;
    const int wid = tid >> 5;
    const int bz = blockIdx.z;
    A += (long)bz * saB;
    B += (long)bz * sbB;
    C += (long)bz * scB;
    const long i0 = (long)blockIdx.y * 128;
    const long j0 = (long)blockIdx.x * 128;

    // ---- staging thread mapping: row = tid>>1 (0..127), k-half = (tid&1)*16 ----
    const int srow = tid >> 1;
    const int skh  = (tid & 1) << 4;
    const float* pA = A + (i0 + srow) * lda + skh;
    const float* pB = B + (j0 + srow) * ldb + skh;
    const int sts_off = (srow * ROWS_B16 + skh) * 2;   // byte offset within array

    // ---- warp tile: wm in {0,1} (64 rows), wn in {0..3} (32 cols) ----
    const int m0 = (wid & 1) * 64;
    const int n0 = (wid >> 1) * 32;
    // ldmatrix lane offsets (bf16 units)
    const int a_base = (m0 + (lane & 15)) * ROWS_B16 + ((lane >> 4) << 3);
    const int b_base = (n0 + ((lane >> 4) << 3) + (lane & 7)) * ROWS_B16 +
                       (((lane >> 3) & 1) << 3);

    float acc[4][4][4];
#pragma unroll
    for (int mt = 0; mt < 4; mt++)
#pragma unroll
        for (int nt = 0; nt < 4; nt++)
#pragma unroll
            for (int e = 0; e < 4; e++) acc[mt][nt][e] = 0.f;

    const int NC = K >> 5;
    float4 ra[4], rb[4];
#pragma unroll
    for (int u = 0; u < 4; u++) {
        ra[u] = *reinterpret_cast<const float4*>(pA + u * 4);
        rb[u] = *reinterpret_cast<const float4*>(pB + u * 4);
    }

    for (int c = 0; c < NC; c++) {
        const int stg = c & 1;
        char* base = smem + stg * STG_B;
        // commit staged chunk (split hi/lo) to smem
#pragma unroll
        for (int u = 0; u < 4; u++) {
            uint32_t hp0, hp1, lp0, lp1;
            split4(ra[u], hp0, hp1, lp0, lp1);
            int off = sts_off + u * 8;
            *reinterpret_cast<uint2*>(base + off)           = make_uint2(hp0, hp1); // Ah
            *reinterpret_cast<uint2*>(base + ARR_B + off)   = make_uint2(lp0, lp1); // Al
            split4(rb[u], hp0, hp1, lp0, lp1);
            *reinterpret_cast<uint2*>(base + 2*ARR_B + off) = make_uint2(hp0, hp1); // Bh
            *reinterpret_cast<uint2*>(base + 3*ARR_B + off) = make_uint2(lp0, lp1); // Bl
        }
        __syncthreads();

        if (c + 1 < NC) {
            pA += KC; pB += KC;
#pragma unroll
            for (int u = 0; u < 4; u++) {
                ra[u] = *reinterpret_cast<const float4*>(pA + u * 4);
                rb[u] = *reinterpret_cast<const float4*>(pB + u * 4);
            }
        }

        const uint32_t sAh = s0 + stg * STG_B;
        const uint32_t sAl = sAh + ARR_B;
        const uint32_t sBh = sAh + 2 * ARR_B;
        const uint32_t sBl = sAh + 3 * ARR_B;

#pragma unroll
        for (int ks = 0; ks < 2; ks++) {
            const int ko = ks * 16;  // bf16 units within row
            uint32_t ah[4][4], bh[4][2], t[4];
            // Ah frags (4 m-tiles)
#pragma unroll
            for (int mt = 0; mt < 4; mt++)
                ldsm4(ah[mt], sAh + (uint32_t)(a_base + mt * 16 * ROWS_B16 + ko) * 2);
            // Bh frags (4 n-tiles, 2 per ldmatrix.x4)
#pragma unroll
            for (int nt2 = 0; nt2 < 2; nt2++) {
                ldsm4(t, sBh + (uint32_t)(b_base + nt2 * 16 * ROWS_B16 + ko) * 2);
                bh[nt2*2][0] = t[0]; bh[nt2*2][1] = t[1];
                bh[nt2*2+1][0] = t[2]; bh[nt2*2+1][1] = t[3];
            }
#pragma unroll
            for (int mt = 0; mt < 4; mt++)
#pragma unroll
                for (int nt = 0; nt < 4; nt++)
                    mma16816(acc[mt][nt], ah[mt], bh[nt]);
            // Bl frags -> Ah*Bl
            uint32_t bl[4][2];
#pragma unroll
            for (int nt2 = 0; nt2 < 2; nt2++) {
                ldsm4(t, sBl + (uint32_t)(b_base + nt2 * 16 * ROWS_B16 + ko) * 2);
                bl[nt2*2][0] = t[0]; bl[nt2*2][1] = t[1];
                bl[nt2*2+1][0] = t[2]; bl[nt2*2+1][1] = t[3];
            }
#pragma unroll
            for (int mt = 0; mt < 4; mt++)
#pragma unroll
                for (int nt = 0; nt < 4; nt++)
                    mma16816(acc[mt][nt], ah[mt], bl[nt]);
            // Al frags -> Al*Bh
#pragma unroll
            for (int mt = 0; mt < 4; mt++) {
                ldsm4(t, sAl + (uint32_t)(a_base + mt * 16 * ROWS_B16 + ko) * 2);
#pragma unroll
                for (int nt = 0; nt < 4; nt++)
                    mma16816(acc[mt][nt], t, bh[nt]);
            }
        }
        __syncthreads();
    }

    // ---- epilogue: acc frag (mt,nt): rows m0+mt*16+lane/4 (+8), cols n0+nt*8+2*(lane%4)
    const int er = lane >> 2;
    const int ec = (lane & 3) << 1;
#pragma unroll
    for (int mt = 0; mt < 4; mt++) {
        long r0 = i0 + m0 + mt * 16 + er;
        long r1 = r0 + 8;
        float bv0 = bias ? bias[r0] : 0.f;
        float bv1 = bias ? bias[r1] : 0.f;
#pragma unroll
        for (int nt = 0; nt < 4; nt++) {
            long jc = j0 + n0 + nt * 8 + ec;
            float2 o0 = make_float2(acc[mt][nt][0] + bv0, acc[mt][nt][1] + bv0);
            float2 o1 = make_float2(acc[mt][nt][2] + bv1, acc[mt][nt][3] + bv1);
            *reinterpret_cast<float2*>(C + r0 * ldc + jc) = o0;
            *reinterpret_cast<float2*>(C + r1 * ldc + jc) = o1;
        }
    }
}

// ================= elementwise kernels =================
// transpose: in [bz][R][Cc] -> out [bz][Cc][R]
__global__ void transpose_kernel(const float* __restrict__ in, float* __restrict__ out,
                                 int R, int Cc)
{
    __shared__ float t[32][33];
    int bx = blockIdx.x * 32, by = blockIdx.y * 32;
    long base = (long)blockIdx.z * (long)R * Cc;
    int x = threadIdx.x, y = threadIdx.y;  // 32 x 8
#pragma unroll
    for (int i = 0; i < 32; i += 8)
        t[y + i][x] = in[base + (long)(by + y + i) * Cc + bx + x];
    __syncthreads();
#pragma unroll
    for (int i = 0; i < 32; i += 8)
        out[base + (long)(bx + y + i) * R + by + x] = t[x][y + i];
}

// 2x2 maxpool: Y [bc][64][64] -> F [bc][32][32]
__global__ void pool_kernel(const float* __restrict__ Y, float* __restrict__ F)
{
    long i = (long)blockIdx.x * blockDim.x + threadIdx.x;
    int ow = (int)(i & 31);
    int oh = (int)((i >> 5) & 31);
    long co = i >> 10;
    const float* y = Y + co * 4096 + (long)(oh * 2) * 64 + ow * 2;
    F[i] = fmaxf(fmaxf(y[0], y[1]), fmaxf(y[64], y[65]));
}

// relu + L2 normalize over q (rows of T[q][p]) per column p.
// block = 256 thr = 64 p-cols x 4 q-slices; grid (PHW/64, BATCH)
__global__ void normcols_kernel(float* __restrict__ T)
{
    __shared__ float part[4][64];
    __shared__ float sinv[64];
    int pp = threadIdx.x & 63, qs = threadIdx.x >> 6;
    int p = blockIdx.x * 64 + pp;
    long base = (long)blockIdx.y * PHW * PHW;
    float ss = 0.f;
#pragma unroll 4
    for (int q = qs * 256; q < qs * 256 + 256; q++) {
        float x = fmaxf(T[base + (long)q * PHW + p], 0.f);
        ss += x * x;
    }
    part[qs][pp] = ss;
    __syncthreads();
    if (threadIdx.x < 64) {
        float s = part[0][threadIdx.x] + part[1][threadIdx.x] +
                  part[2][threadIdx.x] + part[3][threadIdx.x];
        sinv[threadIdx.x] = rsqrtf(s + 1e-6f);
    }
    __syncthreads();
    float inv = sinv[pp];
#pragma unroll 4
    for (int q = qs * 256; q < qs * 256 + 256; q++) {
        long idx = base + (long)q * PHW + p;
        T[idx] = fmaxf(T[idx], 0.f) * inv;
    }
}

// 2x bilinear upsample (align_corners): V [bc][32][32] -> O [bc][64][64]
__global__ void upsample_kernel(const float* __restrict__ V, float* __restrict__ O)
{
    long i = (long)blockIdx.x * blockDim.x + threadIdx.x;
    int x = (int)(i & 63);
    int y = (int)((i >> 6) & 63);
    long co = i >> 12;
    const float s = 31.0f / 63.0f;
    float ys = y * s, xs = x * s;
    int y0 = (int)floorf(ys), x0 = (int)floorf(xs);
    float ty = ys - (float)y0, txx = xs - (float)x0;
    int y1 = min(y0 + 1, 31), x1 = min(x0 + 1, 31);
    const float* v = V + co * 1024;
    float v00 = v[y0 * 32 + x0], v01 = v[y0 * 32 + x1];
    float v10 = v[y1 * 32 + x0], v11 = v[y1 * 32 + x1];
    O[i] = (1.f - ty) * ((1.f - txx) * v00 + txx * v01) +
           ty * ((1.f - txx) * v10 + txx * v11);
}

// ================= launch =================
extern "C" void kernel_launch(void* const* d_in, const int* in_sizes, int n_in,
                              void* d_out, int out_size)
{
    const float* xa      = (const float*)d_in[0];
    const float* xb      = (const float*)d_in[1];
    const float* conv_w  = (const float*)d_in[2];   // (1024,256)
    const float* conv_b  = (const float*)d_in[3];
    const float* We      = (const float*)d_in[4];   // (1024,1024)
    const float* We2     = (const float*)d_in[5];
    const float* conv2_w = (const float*)d_in[6];   // (256,1024)
    const float* conv2_b = (const float*)d_in[7];
    float* out = (float*)d_out;

    float *XT, *Y, *Fa, *Fb, *FaT, *FbT, *WT, *GT, *MT, *ET, *V;
    cudaGetSymbolAddress((void**)&XT,  g_XT);
    cudaGetSymbolAddress((void**)&Y,   g_Y);
    cudaGetSymbolAddress((void**)&Fa,  g_Fa);
    cudaGetSymbolAddress((void**)&Fb,  g_Fb);
    cudaGetSymbolAddress((void**)&FaT, g_FaT);
    cudaGetSymbolAddress((void**)&FbT, g_FbT);
    cudaGetSymbolAddress((void**)&WT,  g_WT);
    cudaGetSymbolAddress((void**)&GT,  g_GT);
    cudaGetSymbolAddress((void**)&MT,  g_MT);
    cudaGetSymbolAddress((void**)&ET,  g_ET);
    cudaGetSymbolAddress((void**)&V,   g_V);

    cudaFuncSetAttribute(tgemm, cudaFuncAttributeMaxDynamicSharedMemorySize, SM_TOTAL);

    const long MM = (long)PHW * C_MID;  // 1024*1024
    dim3 tp(32, 8);

    // --- features: conv1x1 (tensor-core) + pool + transpose, for xa and xb ---
    for (int s = 0; s < 2; s++) {
        const float* x = s ? xb : xa;
        float* F  = s ? Fb : Fa;
        float* FT = s ? FbT : FaT;
        // x [b][256][4096] -> XT [b][4096][256]
        transpose_kernel<<<dim3(128, 8, BATCH), tp>>>(x, XT, C_IN, HW);
        // Y[c,pix] = conv_w[c,:] . XT[pix,:] + b
        tgemm<<<dim3(HW / 128, C_MID / 128, BATCH), 256, SM_TOTAL>>>(
            conv_w, 256, 0,
            XT, C_IN, (long)HW * C_IN,
            Y, HW, (long)C_MID * HW, C_IN, conv_b);
        pool_kernel<<<(BATCH * C_MID * PHW) / 256, 256>>>(Y, F);
        // F [b][1024][1024] -> FT
        transpose_kernel<<<dim3(32, 32, BATCH), tp>>>(F, FT, C_MID, PHW);
    }

    for (int path = 0; path < 2; path++) {
        const float* Wx    = path ? We2 : We;
        const float* Fsrc  = path ? Fb  : Fa;
        const float* FsrcT = path ? FbT : FaT;
        const float* FothT = path ? FaT : FbT;

        // WT[c][d] = Wx[d][c]
        transpose_kernel<<<dim3(32, 32, 1), tp>>>(Wx, WT, C_MID, C_MID);

        // GT[q,c] = sum_d FsrcT[q,d] * WT[c,d]
        tgemm<<<dim3(C_MID / 128, PHW / 128, BATCH), 256, SM_TOTAL>>>(
            FsrcT, C_MID, MM,
            WT, C_MID, 0,
            GT, C_MID, MM, C_MID, nullptr);

        // fmT[q,p] = sum_c GT[q,c] * FothT[p,c]
        tgemm<<<dim3(PHW / 128, PHW / 128, BATCH), 256, SM_TOTAL>>>(
            GT, C_MID, MM,
            FothT, C_MID, MM,
            MT, PHW, MM, C_MID, nullptr);

        // relu + L2 normalize over q (per column p), in place
        normcols_kernel<<<dim3(PHW / 64, BATCH), 256>>>(MT);

        // ET[chan,q] = sum_p Fsrc[chan,p] * MnT[q,p]
        tgemm<<<dim3(PHW / 128, C_MID / 128, BATCH), 256, SM_TOTAL>>>(
            Fsrc, PHW, MM,
            MT, PHW, MM,
            ET, PHW, MM, PHW, nullptr);

        // V[o,s] = sum_q conv2_w[o,q] * ET[s,q] + conv2_b[o]
        tgemm<<<dim3(PHW / 128, 256 / 128, BATCH), 256, SM_TOTAL>>>(
            conv2_w, C_MID, 0,
            ET, C_MID, MM,
            V, PHW, (long)256 * PHW, C_MID, conv2_b);

        // upsample 2x align_corners -> output half
        upsample_kernel<<<(BATCH * 256 * HW) / 256, 256>>>(
            V, out + (long)path * BATCH * 256 * HW);
    }
}

// round 6
// speedup vs baseline: 2.4876x; 1.0596x over previous
#include <cuda_runtime.h>
#include <cuda_bf16.h>
#include <cstdint>

#define BATCH 8
#define C_IN  256
#define C_MID 1024
#define HW    4096   // 64*64
#define PHW   1024   // 32*32
typedef __nv_bfloat16 bf16;

// ---------------- scratch (static device globals; no allocation) ----------------
__device__ bf16 g_XTh[(size_t)BATCH * HW * C_IN];
__device__ bf16 g_XTl[(size_t)BATCH * HW * C_IN];
__device__ bf16 g_Wh [(size_t)C_MID * C_IN];
__device__ bf16 g_Wl [(size_t)C_MID * C_IN];
__device__ bf16 g_Fah[(size_t)BATCH * C_MID * PHW];
__device__ bf16 g_Fal[(size_t)BATCH * C_MID * PHW];
__device__ bf16 g_Fbh[(size_t)BATCH * C_MID * PHW];
__device__ bf16 g_Fbl[(size_t)BATCH * C_MID * PHW];
__device__ bf16 g_FaTh[(size_t)BATCH * PHW * C_MID];
__device__ bf16 g_FaTl[(size_t)BATCH * PHW * C_MID];
__device__ bf16 g_FbTh[(size_t)BATCH * PHW * C_MID];
__device__ bf16 g_FbTl[(size_t)BATCH * PHW * C_MID];
__device__ bf16 g_WTh[(size_t)C_MID * C_MID];
__device__ bf16 g_WTl[(size_t)C_MID * C_MID];
__device__ bf16 g_GTh[(size_t)BATCH * PHW * C_MID];
__device__ bf16 g_GTl[(size_t)BATCH * PHW * C_MID];
__device__ float g_MT[(size_t)BATCH * PHW * PHW];
__device__ bf16 g_MTh[(size_t)BATCH * PHW * PHW];
__device__ bf16 g_MTl[(size_t)BATCH * PHW * PHW];
__device__ bf16 g_ETh[(size_t)BATCH * C_MID * PHW];
__device__ bf16 g_ETl[(size_t)BATCH * C_MID * PHW];
__device__ bf16 g_C2h[(size_t)256 * C_MID];
__device__ bf16 g_C2l[(size_t)256 * C_MID];
__device__ float g_V [(size_t)BATCH * 256 * PHW];

// ================= helpers =================
__device__ __forceinline__ uint32_t smem_u32(const void* p) {
    uint32_t a;
    asm("{ .reg .u64 t; cvta.to.shared.u64 t, %1; cvt.u32.u64 %0, t; }" : "=r"(a) : "l"(p));
    return a;
}
__device__ __forceinline__ void ldsm4(uint32_t* r, uint32_t addr) {
    asm volatile("ldmatrix.sync.aligned.m8n8.x4.shared.b16 {%0,%1,%2,%3}, [%4];"
                 : "=r"(r[0]), "=r"(r[1]), "=r"(r[2]), "=r"(r[3]) : "r"(addr));
}
__device__ __forceinline__ void mma16816(float* d, const uint32_t* a, const uint32_t* b) {
    asm volatile(
        "mma.sync.aligned.m16n8k16.row.col.f32.bf16.bf16.f32 "
        "{%0,%1,%2,%3}, {%4,%5,%6,%7}, {%8,%9}, {%0,%1,%2,%3};"
        : "+f"(d[0]), "+f"(d[1]), "+f"(d[2]), "+f"(d[3])
        : "r"(a[0]), "r"(a[1]), "r"(a[2]), "r"(a[3]), "r"(b[0]), "r"(b[1]));
}
// pack two floats (lo=x at lower addr, hi=y) into bf16x2
__device__ __forceinline__ uint32_t packbf(float x, float y) {
    uint32_t r;
    asm("cvt.rn.bf16x2.f32 %0, %1, %2;" : "=r"(r) : "f"(y), "f"(x));
    return r;
}
__device__ __forceinline__ float bflo(uint32_t p) { return __uint_as_float(p << 16); }
__device__ __forceinline__ float bfhi(uint32_t p) { return __uint_as_float(p & 0xFFFF0000u); }

// ================= tensor GEMM via mma.sync, pre-split bf16 operands ==========
// C[i,j](+bias[i]) = sum_k (Ah+Al)[i,k] * (Bh+Bl)[j,k]  (3-term split product)
// mode 0: write fp32 C.  mode 1: write split bf16 Ch/Cl.
// mode 2: conv1 pooled epilogue: 2x2 maxpool over pix cols (j-tile = 2 image rows),
//         +bias, write split bf16 Ch/Cl as F[c][q] (ldc applies, q0 = j0>>2).
#define KC        32
#define ROWS_B16  40
#define ARR_B     10240     // 128 * 40 * 2
#define STG_B     40960
#define SM_TOTAL  81920

__global__ __launch_bounds__(256, 1) void tgemm(
    const bf16* __restrict__ Ah, const bf16* __restrict__ Al, long lda, long saB,
    const bf16* __restrict__ Bh, const bf16* __restrict__ Bl, long ldb, long sbB,
    float* __restrict__ C, bf16* __restrict__ Ch, bf16* __restrict__ Cl,
    long ldc, long scB, int K, const float* __restrict__ bias, int mode)
{
    extern __shared__ char smem[];
    const uint32_t s0 = smem_u32(smem);
    const int tid = threadIdx.x;
    const int lane = tid & 31;
    const int wid = tid >> 5;
    const int bz = blockIdx.z;
    Ah += (long)bz * saB; Al += (long)bz * saB;
    Bh += (long)bz * sbB; Bl += (long)bz * sbB;
    const long i0 = (long)blockIdx.y * 128;
    const long j0 = (long)blockIdx.x * 128;

    // staging: row = tid>>1 (0..127), k-half = (tid&1)*16
    const int srow = tid >> 1;
    const int skh  = (tid & 1) << 4;
    const bf16* pAh = Ah + (i0 + srow) * lda + skh;
    const bf16* pAl = Al + (i0 + srow) * lda + skh;
    const bf16* pBh = Bh + (j0 + srow) * ldb + skh;
    const bf16* pBl = Bl + (j0 + srow) * ldb + skh;
    const int sts_off = (srow * ROWS_B16 + skh) * 2;

    const int m0 = (wid & 1) * 64;
    const int n0 = (wid >> 1) * 32;
    const int a_base = (m0 + (lane & 15)) * ROWS_B16 + ((lane >> 4) << 3);
    const int b_base = (n0 + ((lane >> 4) << 3) + (lane & 7)) * ROWS_B16 +
                       (((lane >> 3) & 1) << 3);

    float acc[4][4][4];
#pragma unroll
    for (int mt = 0; mt < 4; mt++)
#pragma unroll
        for (int nt = 0; nt < 4; nt++)
#pragma unroll
            for (int e = 0; e < 4; e++) acc[mt][nt][e] = 0.f;

    const int NC = K >> 5;
    uint4 rg[8];
    rg[0] = *reinterpret_cast<const uint4*>(pAh);
    rg[1] = *reinterpret_cast<const uint4*>(pAh + 8);
    rg[2] = *reinterpret_cast<const uint4*>(pAl);
    rg[3] = *reinterpret_cast<const uint4*>(pAl + 8);
    rg[4] = *reinterpret_cast<const uint4*>(pBh);
    rg[5] = *reinterpret_cast<const uint4*>(pBh + 8);
    rg[6] = *reinterpret_cast<const uint4*>(pBl);
    rg[7] = *reinterpret_cast<const uint4*>(pBl + 8);

    for (int c = 0; c < NC; c++) {
        const int stg = c & 1;
        char* base = smem + stg * STG_B;
        *reinterpret_cast<uint4*>(base + sts_off)                 = rg[0];
        *reinterpret_cast<uint4*>(base + sts_off + 16)            = rg[1];
        *reinterpret_cast<uint4*>(base + ARR_B + sts_off)         = rg[2];
        *reinterpret_cast<uint4*>(base + ARR_B + sts_off + 16)    = rg[3];
        *reinterpret_cast<uint4*>(base + 2*ARR_B + sts_off)       = rg[4];
        *reinterpret_cast<uint4*>(base + 2*ARR_B + sts_off + 16)  = rg[5];
        *reinterpret_cast<uint4*>(base + 3*ARR_B + sts_off)       = rg[6];
        *reinterpret_cast<uint4*>(base + 3*ARR_B + sts_off + 16)  = rg[7];
        __syncthreads();

        if (c + 1 < NC) {
            pAh += KC; pAl += KC; pBh += KC; pBl += KC;
            rg[0] = *reinterpret_cast<const uint4*>(pAh);
            rg[1] = *reinterpret_cast<const uint4*>(pAh + 8);
            rg[2] = *reinterpret_cast<const uint4*>(pAl);
            rg[3] = *reinterpret_cast<const uint4*>(pAl + 8);
            rg[4] = *reinterpret_cast<const uint4*>(pBh);
            rg[5] = *reinterpret_cast<const uint4*>(pBh + 8);
            rg[6] = *reinterpret_cast<const uint4*>(pBl);
            rg[7] = *reinterpret_cast<const uint4*>(pBl + 8);
        }

        const uint32_t sAh = s0 + stg * STG_B;
        const uint32_t sAl = sAh + ARR_B;
        const uint32_t sBh = sAh + 2 * ARR_B;
        const uint32_t sBl = sAh + 3 * ARR_B;

#pragma unroll
        for (int ks = 0; ks < 2; ks++) {
            const int ko = ks * 16;
            uint32_t ah[4][4], bh[4][2], t[4];
#pragma unroll
            for (int mt = 0; mt < 4; mt++)
                ldsm4(ah[mt], sAh + (uint32_t)(a_base + mt * 16 * ROWS_B16 + ko) * 2);
#pragma unroll
            for (int nt2 = 0; nt2 < 2; nt2++) {
                ldsm4(t, sBh + (uint32_t)(b_base + nt2 * 16 * ROWS_B16 + ko) * 2);
                bh[nt2*2][0] = t[0]; bh[nt2*2][1] = t[1];
                bh[nt2*2+1][0] = t[2]; bh[nt2*2+1][1] = t[3];
            }
#pragma unroll
            for (int mt = 0; mt < 4; mt++)
#pragma unroll
                for (int nt = 0; nt < 4; nt++)
                    mma16816(acc[mt][nt], ah[mt], bh[nt]);
            uint32_t bl[4][2];
#pragma unroll
            for (int nt2 = 0; nt2 < 2; nt2++) {
                ldsm4(t, sBl + (uint32_t)(b_base + nt2 * 16 * ROWS_B16 + ko) * 2);
                bl[nt2*2][0] = t[0]; bl[nt2*2][1] = t[1];
                bl[nt2*2+1][0] = t[2]; bl[nt2*2+1][1] = t[3];
            }
#pragma unroll
            for (int mt = 0; mt < 4; mt++)
#pragma unroll
                for (int nt = 0; nt < 4; nt++)
                    mma16816(acc[mt][nt], ah[mt], bl[nt]);
#pragma unroll
            for (int mt = 0; mt < 4; mt++) {
                ldsm4(t, sAl + (uint32_t)(a_base + mt * 16 * ROWS_B16 + ko) * 2);
#pragma unroll
                for (int nt = 0; nt < 4; nt++)
                    mma16816(acc[mt][nt], t, bh[nt]);
            }
        }
        __syncthreads();
    }

    const int er = lane >> 2;
    const int ec = (lane & 3) << 1;

    if (mode == 2) {
        // pooled epilogue: dump tile to smem, 2x2 maxpool over pix, +bias, split write
        float* spool = reinterpret_cast<float*>(smem);   // 128 x 132
#pragma unroll
        for (int mt = 0; mt < 4; mt++) {
            int r0 = m0 + mt * 16 + er;
#pragma unroll
            for (int nt = 0; nt < 4; nt++) {
                int jc = n0 + nt * 8 + ec;
                *reinterpret_cast<float2*>(&spool[(r0)     * 132 + jc]) =
                    make_float2(acc[mt][nt][0], acc[mt][nt][1]);
                *reinterpret_cast<float2*>(&spool[(r0 + 8) * 132 + jc]) =
                    make_float2(acc[mt][nt][2], acc[mt][nt][3]);
            }
        }
        __syncthreads();
        const int cl = tid >> 1;           // channel row 0..127
        const int half = tid & 1;          // ow half
        const float bv = bias[i0 + cl];
        uint32_t hw[8], lw[8];
#pragma unroll
        for (int o = 0; o < 16; o += 2) {
            float vv[2];
#pragma unroll
            for (int u = 0; u < 2; u++) {
                int owg = half * 16 + o + u;
                float2 a0 = *reinterpret_cast<float2*>(&spool[cl * 132 + 2 * owg]);
                float2 a1 = *reinterpret_cast<float2*>(&spool[cl * 132 + 64 + 2 * owg]);
                vv[u] = fmaxf(fmaxf(a0.x, a0.y), fmaxf(a1.x, a1.y)) + bv;
            }
            uint32_t hp = packbf(vv[0], vv[1]);
            hw[o >> 1] = hp;
            lw[o >> 1] = packbf(vv[0] - bflo(hp), vv[1] - bfhi(hp));
        }
        long q0 = (long)(j0 >> 2) + half * 16;     // (j0/128)*32 + half*16
        long off = (long)bz * scB + (i0 + cl) * ldc + q0;
        *reinterpret_cast<uint4*>(Ch + off)     = *reinterpret_cast<uint4*>(hw);
        *reinterpret_cast<uint4*>(Ch + off + 8) = *reinterpret_cast<uint4*>(hw + 4);
        *reinterpret_cast<uint4*>(Cl + off)     = *reinterpret_cast<uint4*>(lw);
        *reinterpret_cast<uint4*>(Cl + off + 8) = *reinterpret_cast<uint4*>(lw + 4);
        return;
    }

#pragma unroll
    for (int mt = 0; mt < 4; mt++) {
        long r0 = i0 + m0 + mt * 16 + er;
        long r1 = r0 + 8;
        float bv0 = bias ? bias[r0] : 0.f;
        float bv1 = bias ? bias[r1] : 0.f;
#pragma unroll
        for (int nt = 0; nt < 4; nt++) {
            long jc = j0 + n0 + nt * 8 + ec;
            float o00 = acc[mt][nt][0] + bv0, o01 = acc[mt][nt][1] + bv0;
            float o10 = acc[mt][nt][2] + bv1, o11 = acc[mt][nt][3] + bv1;
            if (mode == 0) {
                float* cb = C + (long)bz * scB;
                *reinterpret_cast<float2*>(cb + r0 * ldc + jc) = make_float2(o00, o01);
                *reinterpret_cast<float2*>(cb + r1 * ldc + jc) = make_float2(o10, o11);
            } else {
                bf16* chb = Ch + (long)bz * scB;
                bf16* clb = Cl + (long)bz * scB;
                uint32_t h0 = packbf(o00, o01);
                uint32_t h1 = packbf(o10, o11);
                *reinterpret_cast<uint32_t*>(chb + r0 * ldc + jc) = h0;
                *reinterpret_cast<uint32_t*>(chb + r1 * ldc + jc) = h1;
                *reinterpret_cast<uint32_t*>(clb + r0 * ldc + jc) =
                    packbf(o00 - bflo(h0), o01 - bfhi(h0));
                *reinterpret_cast<uint32_t*>(clb + r1 * ldc + jc) =
                    packbf(o10 - bflo(h1), o11 - bfhi(h1));
            }
        }
    }
}

// ================= conversion / movement kernels =================
// fp32 [bz][R][Cc] -> split bf16 [bz][Cc][R]
__global__ void trans_split_kernel(const float* __restrict__ in,
                                   bf16* __restrict__ oh, bf16* __restrict__ ol,
                                   int R, int Cc)
{
    __shared__ float t[32][33];
    int bx = blockIdx.x * 32, by = blockIdx.y * 32;
    long base = (long)blockIdx.z * (long)R * Cc;
    int x = threadIdx.x, y = threadIdx.y;  // 32 x 8
#pragma unroll
    for (int i = 0; i < 32; i += 8)
        t[y + i][x] = in[base + (long)(by + y + i) * Cc + bx + x];
    __syncthreads();
#pragma unroll
    for (int i = 0; i < 32; i += 8) {
        float v = t[x][y + i];
        bf16 h = __float2bfloat16(v);
        long o = base + (long)(bx + y + i) * R + by + x;
        oh[o] = h;
        ol[o] = __float2bfloat16(v - __bfloat162float(h));
    }
}

// fp32 flat -> split bf16 flat
__global__ void split_kernel(const float* __restrict__ in,
                             bf16* __restrict__ oh, bf16* __restrict__ ol, int n)
{
    int i = blockIdx.x * 256 + threadIdx.x;
    if (i >= n) return;
    float v = in[i];
    bf16 h = __float2bfloat16(v);
    oh[i] = h;
    ol[i] = __float2bfloat16(v - __bfloat162float(h));
}

// bf16 [bz][R][Cc] -> [bz][Cc][R]  (two arrays at once)
__global__ void trans_b16_kernel(const bf16* __restrict__ ih, const bf16* __restrict__ il,
                                 bf16* __restrict__ oh, bf16* __restrict__ ol,
                                 int R, int Cc)
{
    __shared__ bf16 th[32][34];
    __shared__ bf16 tl[32][34];
    int bx = blockIdx.x * 32, by = blockIdx.y * 32;
    long base = (long)blockIdx.z * (long)R * Cc;
    int x = threadIdx.x, y = threadIdx.y;
#pragma unroll
    for (int i = 0; i < 32; i += 8) {
        long o = base + (long)(by + y + i) * Cc + bx + x;
        th[y + i][x] = ih[o];
        tl[y + i][x] = il[o];
    }
    __syncthreads();
#pragma unroll
    for (int i = 0; i < 32; i += 8) {
        long o = base + (long)(bx + y + i) * R + by + x;
        oh[o] = th[x][y + i];
        ol[o] = tl[x][y + i];
    }
}

// relu + L2 normalize over q (rows of T[q][p]) per column p; write split bf16.
// block 256 = 64 p x 4 q-slices; grid (PHW/64, BATCH)
__global__ void normsplit_kernel(const float* __restrict__ T,
                                 bf16* __restrict__ oh, bf16* __restrict__ ol)
{
    __shared__ float part[4][64];
    __shared__ float sinv[64];
    int pp = threadIdx.x & 63, qs = threadIdx.x >> 6;
    int p = blockIdx.x * 64 + pp;
    long base = (long)blockIdx.y * PHW * PHW;
    float ss = 0.f;
#pragma unroll 4
    for (int q = qs * 256; q < qs * 256 + 256; q++) {
        float x = fmaxf(T[base + (long)q * PHW + p], 0.f);
        ss += x * x;
    }
    part[qs][pp] = ss;
    __syncthreads();
    if (threadIdx.x < 64) {
        float s = part[0][threadIdx.x] + part[1][threadIdx.x] +
                  part[2][threadIdx.x] + part[3][threadIdx.x];
        sinv[threadIdx.x] = rsqrtf(s + 1e-6f);
    }
    __syncthreads();
    float inv = sinv[pp];
#pragma unroll 4
    for (int q = qs * 256; q < qs * 256 + 256; q++) {
        long idx = base + (long)q * PHW + p;
        float v = fmaxf(T[idx], 0.f) * inv;
        bf16 h = __float2bfloat16(v);
        oh[idx] = h;
        ol[idx] = __float2bfloat16(v - __bfloat162float(h));
    }
}

// 2x bilinear upsample (align_corners): V [bc][32][32] -> O [bc][64][64]
__global__ void upsample_kernel(const float* __restrict__ V, float* __restrict__ O)
{
    long i = (long)blockIdx.x * blockDim.x + threadIdx.x;
    int x = (int)(i & 63);
    int y = (int)((i >> 6) & 63);
    long co = i >> 12;
    const float s = 31.0f / 63.0f;
    float ys = y * s, xs = x * s;
    int y0 = (int)floorf(ys), x0 = (int)floorf(xs);
    float ty = ys - (float)y0, txx = xs - (float)x0;
    int y1 = min(y0 + 1, 31), x1 = min(x0 + 1, 31);
    const float* v = V + co * 1024;
    float v00 = v[y0 * 32 + x0], v01 = v[y0 * 32 + x1];
    float v10 = v[y1 * 32 + x0], v11 = v[y1 * 32 + x1];
    O[i] = (1.f - ty) * ((1.f - txx) * v00 + txx * v01) +
           ty * ((1.f - txx) * v10 + txx * v11);
}

// ================= launch =================
extern "C" void kernel_launch(void* const* d_in, const int* in_sizes, int n_in,
                              void* d_out, int out_size)
{
    const float* xa      = (const float*)d_in[0];
    const float* xb      = (const float*)d_in[1];
    const float* conv_w  = (const float*)d_in[2];
    const float* conv_b  = (const float*)d_in[3];
    const float* We      = (const float*)d_in[4];
    const float* We2     = (const float*)d_in[5];
    const float* conv2_w = (const float*)d_in[6];
    const float* conv2_b = (const float*)d_in[7];
    float* out = (float*)d_out;

    bf16 *XTh, *XTl, *Wh, *Wl, *Fah, *Fal, *Fbh, *Fbl;
    bf16 *FaTh, *FaTl, *FbTh, *FbTl, *WTh, *WTl, *GTh, *GTl;
    bf16 *MTh, *MTl, *ETh, *ETl, *C2h, *C2l;
    float *MT, *V;
    cudaGetSymbolAddress((void**)&XTh, g_XTh);  cudaGetSymbolAddress((void**)&XTl, g_XTl);
    cudaGetSymbolAddress((void**)&Wh,  g_Wh);   cudaGetSymbolAddress((void**)&Wl,  g_Wl);
    cudaGetSymbolAddress((void**)&Fah, g_Fah);  cudaGetSymbolAddress((void**)&Fal, g_Fal);
    cudaGetSymbolAddress((void**)&Fbh, g_Fbh);  cudaGetSymbolAddress((void**)&Fbl, g_Fbl);
    cudaGetSymbolAddress((void**)&FaTh,g_FaTh); cudaGetSymbolAddress((void**)&FaTl,g_FaTl);
    cudaGetSymbolAddress((void**)&FbTh,g_FbTh); cudaGetSymbolAddress((void**)&FbTl,g_FbTl);
    cudaGetSymbolAddress((void**)&WTh, g_WTh);  cudaGetSymbolAddress((void**)&WTl, g_WTl);
    cudaGetSymbolAddress((void**)&GTh, g_GTh);  cudaGetSymbolAddress((void**)&GTl, g_GTl);
    cudaGetSymbolAddress((void**)&MT,  g_MT);
    cudaGetSymbolAddress((void**)&MTh, g_MTh);  cudaGetSymbolAddress((void**)&MTl, g_MTl);
    cudaGetSymbolAddress((void**)&ETh, g_ETh);  cudaGetSymbolAddress((void**)&ETl, g_ETl);
    cudaGetSymbolAddress((void**)&C2h, g_C2h);  cudaGetSymbolAddress((void**)&C2l, g_C2l);
    cudaGetSymbolAddress((void**)&V,   g_V);

    cudaFuncSetAttribute(tgemm, cudaFuncAttributeMaxDynamicSharedMemorySize, SM_TOTAL);

    const long MM = (long)PHW * C_MID;
    dim3 tp(32, 8);

    // weights -> split bf16 (K-contiguous already)
    split_kernel<<<(C_MID * C_IN + 255) / 256, 256>>>(conv_w, Wh, Wl, C_MID * C_IN);
    split_kernel<<<(256 * C_MID + 255) / 256, 256>>>(conv2_w, C2h, C2l, 256 * C_MID);

    // features: transpose+split x, conv1 GEMM with fused pool -> split F, transpose F
    for (int s = 0; s < 2; s++) {
        const float* x = s ? xb : xa;
        bf16* Fh = s ? Fbh : Fah;  bf16* Fl = s ? Fbl : Fal;
        bf16* FTh = s ? FbTh : FaTh;  bf16* FTl = s ? FbTl : FaTl;
        trans_split_kernel<<<dim3(128, 8, BATCH), tp>>>(x, XTh, XTl, C_IN, HW);
        tgemm<<<dim3(HW / 128, C_MID / 128, BATCH), 256, SM_TOTAL>>>(
            Wh, Wl, C_IN, 0,
            XTh, XTl, C_IN, (long)HW * C_IN,
            nullptr, Fh, Fl, PHW, MM, C_IN, conv_b, 2);
        trans_b16_kernel<<<dim3(32, 32, BATCH), tp>>>(Fh, Fl, FTh, FTl, C_MID, PHW);
    }

    for (int path = 0; path < 2; path++) {
        const float* Wx = path ? We2 : We;
        bf16* Fsh  = path ? Fbh  : Fah;   bf16* Fsl  = path ? Fbl  : Fal;
        bf16* FsTh = path ? FbTh : FaTh;  bf16* FsTl = path ? FbTl : FaTl;
        bf16* FoTh = path ? FaTh : FbTh;  bf16* FoTl = path ? FaTl : FbTl;

        // WT[c][d] = Wx[d][c], split
        trans_split_kernel<<<dim3(32, 32, 1), tp>>>(Wx, WTh, WTl, C_MID, C_MID);

        // GT[q,c] = sum_d FsT[q,d] * WT[c,d]  -> split
        tgemm<<<dim3(C_MID / 128, PHW / 128, BATCH), 256, SM_TOTAL>>>(
            FsTh, FsTl, C_MID, MM,
            WTh, WTl, C_MID, 0,
            nullptr, GTh, GTl, C_MID, MM, C_MID, nullptr, 1);

        // fmT[q,p] = sum_c GT[q,c] * FoT[p,c]  -> fp32 MT
        tgemm<<<dim3(PHW / 128, PHW / 128, BATCH), 256, SM_TOTAL>>>(
            GTh, GTl, C_MID, MM,
            FoTh, FoTl, C_MID, MM,
            MT, nullptr, nullptr, PHW, MM, C_MID, nullptr, 0);

        // relu + L2 norm over q, write split
        normsplit_kernel<<<dim3(PHW / 64, BATCH), 256>>>(MT, MTh, MTl);

        // ET[k,q] = sum_p Fs[k,p] * Mn[q,p]  -> split
        tgemm<<<dim3(PHW / 128, C_MID / 128, BATCH), 256, SM_TOTAL>>>(
            Fsh, Fsl, PHW, MM,
            MTh, MTl, PHW, MM,
            nullptr, ETh, ETl, PHW, MM, PHW, nullptr, 1);

        // V[o,k] = sum_q c2w[o,q] * ET[k,q] + b  -> fp32
        tgemm<<<dim3(PHW / 128, 256 / 128, BATCH), 256, SM_TOTAL>>>(
            C2h, C2l, C_MID, 0,
            ETh, ETl, C_MID, MM,
            V, nullptr, nullptr, PHW, (long)256 * PHW, C_MID, conv2_b, 0);

        upsample_kernel<<<(BATCH * 256 * HW) / 256, 256>>>(
            V, out + (long)path * BATCH * 256 * HW);
    }
}